// round 2
// baseline (speedup 1.0000x reference)
#include <cuda_runtime.h>
#include <cuda_bf16.h>

#define TOKENS 4096
#define DDIM 768
#define FDIM 3072
#define NEXP 8

// Scratch (allocation-free rule: __device__ globals)
__device__ float g_h1[(size_t)TOKENS * FDIM];   // 48 MB intermediate activations
__device__ float g_prob[TOKENS];
__device__ int   g_bucket[NEXP * TOKENS];
__device__ int   g_count[NEXP];

__global__ void reset_kernel() {
    if (threadIdx.x < NEXP) g_count[threadIdx.x] = 0;
}

// One warp per token: fp32 logits, softmax, argmax, bucket insert.
__global__ void router_kernel(const float* __restrict__ x,
                              const float* __restrict__ wr,
                              float* __restrict__ dout,
                              int has_logits, int has_index) {
    int warp = threadIdx.x >> 5, lane = threadIdx.x & 31;
    int t = blockIdx.x * 8 + warp;
    if (t >= TOKENS) return;
    float acc[NEXP];
#pragma unroll
    for (int e = 0; e < NEXP; e++) acc[e] = 0.f;
    const float* xr = x + (size_t)t * DDIM;
    for (int d = lane; d < DDIM; d += 32) {
        float xv = xr[d];
#pragma unroll
        for (int e = 0; e < NEXP; e++) acc[e] += xv * wr[d * NEXP + e];
    }
#pragma unroll
    for (int e = 0; e < NEXP; e++) {
#pragma unroll
        for (int o = 16; o; o >>= 1)
            acc[e] += __shfl_xor_sync(0xffffffffu, acc[e], o);
    }
    if (lane == 0) {
        float mx = acc[0]; int mi = 0;
#pragma unroll
        for (int e = 1; e < NEXP; e++)
            if (acc[e] > mx) { mx = acc[e]; mi = e; }
        float s = 0.f;
#pragma unroll
        for (int e = 0; e < NEXP; e++) s += expf(acc[e] - mx);
        g_prob[t] = 1.0f / s;                     // top-1 softmax prob
        int slot = atomicAdd(&g_count[mi], 1);
        g_bucket[mi * TOKENS + slot] = t;
        if (has_logits) {
            float* lg = dout + (size_t)TOKENS * DDIM + (size_t)t * NEXP;
#pragma unroll
            for (int e = 0; e < NEXP; e++) lg[e] = acc[e];
        }
        if (has_index)
            dout[(size_t)TOKENS * DDIM + (size_t)TOKENS * NEXP + t] = (float)mi;
    }
}

// Gather-GEMM over per-expert token buckets.
// FIRST:  C(h1)[tok, :] = relu( x[tok,:] @ w1[e] + b1[e] )       KD=768,  ND=3072
// !FIRST: out[tok, :]   = ( h1[tok,:] @ w2[e] + b2[e] ) * prob   KD=3072, ND=768
template<int BM, int BN, int KD, int ND, bool FIRST>
__global__ __launch_bounds__(256, 2)
void moe_gemm(const float* __restrict__ Asrc,
              const float* __restrict__ W,
              const float* __restrict__ bias,
              float* __restrict__ Cout) {
    const int e = blockIdx.z;
    const int cnt = g_count[e];
    const int row0 = blockIdx.y * BM;
    if (row0 >= cnt) return;
    const int col0 = blockIdx.x * BN;

    const float* __restrict__ A  = FIRST ? Asrc : g_h1;
    float* __restrict__ C        = FIRST ? g_h1 : Cout;
    const float* __restrict__ Wb = W + (size_t)e * KD * ND;
    const float* __restrict__ bb = bias + e * ND;

    __shared__ float As[8][BM];
    __shared__ float Bs[8][BN];
    __shared__ int stok[BM];

    const int tid = threadIdx.x;
    for (int i = tid; i < BM; i += 256) {
        int r = row0 + i;
        stok[i] = (r < cnt) ? g_bucket[e * TOKENS + r] : -1;
    }
    __syncthreads();

    const int tx = tid & 15;
    const int ty = tid >> 4;
    constexpr int TM = BM / 16;
    constexpr int TN = BN / 16;

    float accu[TM][TN];
#pragma unroll
    for (int i = 0; i < TM; i++)
#pragma unroll
        for (int j = 0; j < TN; j++) accu[i][j] = 0.f;

    for (int kk = 0; kk < KD; kk += 8) {
        // A tile: BM rows x 8 cols, gathered; 2 float4 segments per row
        for (int i = tid; i < BM * 2; i += 256) {
            int m = i >> 1;
            int seg = i & 1;
            int tok = stok[m];
            float4 v = make_float4(0.f, 0.f, 0.f, 0.f);
            if (tok >= 0)
                v = *reinterpret_cast<const float4*>(
                        A + (size_t)tok * KD + kk + seg * 4);
            As[seg * 4 + 0][m] = v.x;
            As[seg * 4 + 1][m] = v.y;
            As[seg * 4 + 2][m] = v.z;
            As[seg * 4 + 3][m] = v.w;
        }
        // B tile: 8 rows x BN cols of W (row-major [KD x ND])
        for (int i = tid; i < BN * 2; i += 256) {
            int kr = i / (BN / 4);
            int c4 = i % (BN / 4);
            *reinterpret_cast<float4*>(&Bs[kr][c4 * 4]) =
                *reinterpret_cast<const float4*>(
                    Wb + (size_t)(kk + kr) * ND + col0 + c4 * 4);
        }
        __syncthreads();
#pragma unroll
        for (int k = 0; k < 8; k++) {
            float aR[TM], bR[TN];
#pragma unroll
            for (int i = 0; i < TM; i += 4)
                *reinterpret_cast<float4*>(&aR[i]) =
                    *reinterpret_cast<const float4*>(&As[k][ty * TM + i]);
#pragma unroll
            for (int j = 0; j < TN; j += 4)
                *reinterpret_cast<float4*>(&bR[j]) =
                    *reinterpret_cast<const float4*>(&Bs[k][tx * TN + j]);
#pragma unroll
            for (int i = 0; i < TM; i++)
#pragma unroll
                for (int j = 0; j < TN; j++)
                    accu[i][j] += aR[i] * bR[j];
        }
        __syncthreads();
    }

    float bv[TN];
#pragma unroll
    for (int j = 0; j < TN; j++) bv[j] = bb[col0 + tx * TN + j];

#pragma unroll
    for (int i = 0; i < TM; i++) {
        int m = ty * TM + i;
        int tok = stok[m];
        if (tok < 0) continue;
        float* cr = C + (size_t)tok * ND + col0 + tx * TN;
        if (FIRST) {
#pragma unroll
            for (int j = 0; j < TN; j++) {
                float v = accu[i][j] + bv[j];
                cr[j] = v > 0.f ? v : 0.f;
            }
        } else {
            float p = g_prob[tok];
#pragma unroll
            for (int j = 0; j < TN; j++)
                cr[j] = (accu[i][j] + bv[j]) * p;
        }
    }
}

extern "C" void kernel_launch(void* const* d_in, const int* in_sizes, int n_in,
                              void* d_out, int out_size) {
    const float* x   = (const float*)d_in[0];   // [4,1024,768]
    const float* wr  = (const float*)d_in[1];   // [768,8]
    const float* w1  = (const float*)d_in[2];   // [8,768,3072]
    const float* b1  = (const float*)d_in[3];   // [8,3072]
    const float* w2  = (const float*)d_in[4];   // [8,3072,768]
    const float* b2  = (const float*)d_in[5];   // [8,768]
    float* out = (float*)d_out;

    const int hid = TOKENS * DDIM;
    int has_logits = (out_size >= hid + TOKENS * NEXP) ? 1 : 0;
    int has_index  = (out_size >= hid + TOKENS * NEXP + TOKENS) ? 1 : 0;

    reset_kernel<<<1, 32>>>();
    router_kernel<<<TOKENS / 8, 256>>>(x, wr, out, has_logits, has_index);

    // GEMM1: [cnt x 768] @ [768 x 3072] -> relu -> g_h1
    moe_gemm<128, 128, DDIM, FDIM, true>
        <<<dim3(FDIM / 128, TOKENS / 128, NEXP), 256>>>(x, w1, b1, out);

    // GEMM2: [cnt x 3072] @ [3072 x 768] -> *prob -> out
    moe_gemm<128, 64, FDIM, DDIM, false>
        <<<dim3(DDIM / 64, TOKENS / 128, NEXP), 256>>>(x, w2, b2, out);
}

// round 6
// speedup vs baseline: 2.0811x; 2.0811x over previous
#include <cuda_runtime.h>
#include <cuda_bf16.h>
#include <cstdint>

#define TOKENS 4096
#define DDIM 768
#define FDIM 3072
#define NEXP 8

// ---------------- scratch (__device__ globals; no allocs allowed) ----------
__device__ float g_h1[(size_t)TOKENS * FDIM];   // fp32 intermediate, 48 MB
__device__ float g_prob[TOKENS];
__device__ int   g_bucket[NEXP * TOKENS];
__device__ int   g_count[NEXP];
__device__ __nv_bfloat16 g_w1t_hi[(size_t)NEXP * FDIM * DDIM];  // [e][f][d]
__device__ __nv_bfloat16 g_w1t_lo[(size_t)NEXP * FDIM * DDIM];
__device__ __nv_bfloat16 g_w2t_hi[(size_t)NEXP * DDIM * FDIM];  // [e][d][f]
__device__ __nv_bfloat16 g_w2t_lo[(size_t)NEXP * DDIM * FDIM];

// ---------------- PTX helpers (baseline ISA only) ---------------------------
__device__ __forceinline__ uint32_t smem_to_u32(const void* p) {
    uint32_t a;
    asm("{ .reg .u64 t; cvta.to.shared.u64 t, %1; cvt.u32.u64 %0, t; }"
        : "=r"(a) : "l"(p));
    return a;
}

#define CP16(dst, src) \
    asm volatile("cp.async.cg.shared.global [%0], [%1], 16;" \
                 :: "r"(dst), "l"(src) : "memory")

#define STS128(r0, r1, r2, r3, smem_addr) \
    asm volatile("st.shared.v4.b32 [%0], {%1, %2, %3, %4};" \
                 :: "r"(smem_addr), "r"(r0), "r"(r1), "r"(r2), "r"(r3) : "memory")

#define LDSM4(r, addr) \
    asm volatile("ldmatrix.sync.aligned.m8n8.x4.shared.b16 {%0,%1,%2,%3}, [%4];" \
                 : "=r"((r)[0]), "=r"((r)[1]), "=r"((r)[2]), "=r"((r)[3]) \
                 : "r"(addr))

#define MMA(c, a, b0, b1) \
    asm volatile("mma.sync.aligned.m16n8k16.row.col.f32.bf16.bf16.f32 " \
                 "{%0,%1,%2,%3}, {%4,%5,%6,%7}, {%8,%9}, {%0,%1,%2,%3};" \
                 : "+f"((c)[0]), "+f"((c)[1]), "+f"((c)[2]), "+f"((c)[3]) \
                 : "r"((a)[0]), "r"((a)[1]), "r"((a)[2]), "r"((a)[3]), \
                   "r"(b0), "r"(b1))

// bf16 split helpers: value = hi + lo, hi = bf16(v), lo = bf16(v - hi)
__device__ __forceinline__ uint32_t bf16hi2(float a, float b) {
    return (uint32_t)__bfloat16_as_ushort(__float2bfloat16(a)) |
           ((uint32_t)__bfloat16_as_ushort(__float2bfloat16(b)) << 16);
}
__device__ __forceinline__ float bf16res(float a) {
    return a - __bfloat162float(__float2bfloat16(a));
}

// swizzled byte offset of 16B unit u (0/1) in row 'row' (32B rows)
__device__ __forceinline__ uint32_t sw(uint32_t row, uint32_t u) {
    return row * 32 + (((u) ^ (row >> 2)) & 1u) * 16;
}

// ---------------- small kernels --------------------------------------------
__global__ void reset_kernel() {
    if (threadIdx.x < NEXP) g_count[threadIdx.x] = 0;
}

__global__ void router_kernel(const float* __restrict__ x,
                              const float* __restrict__ wr,
                              float* __restrict__ dout,
                              int has_logits, int has_index) {
    int warp = threadIdx.x >> 5, lane = threadIdx.x & 31;
    int t = blockIdx.x * 8 + warp;
    if (t >= TOKENS) return;
    float acc[NEXP];
#pragma unroll
    for (int e = 0; e < NEXP; e++) acc[e] = 0.f;
    const float* xr = x + (size_t)t * DDIM;
    for (int d = lane; d < DDIM; d += 32) {
        float xv = xr[d];
#pragma unroll
        for (int e = 0; e < NEXP; e++) acc[e] += xv * wr[d * NEXP + e];
    }
#pragma unroll
    for (int e = 0; e < NEXP; e++) {
#pragma unroll
        for (int o = 16; o; o >>= 1)
            acc[e] += __shfl_xor_sync(0xffffffffu, acc[e], o);
    }
    if (lane == 0) {
        float mx = acc[0]; int mi = 0;
#pragma unroll
        for (int e = 1; e < NEXP; e++)
            if (acc[e] > mx) { mx = acc[e]; mi = e; }
        float s = 0.f;
#pragma unroll
        for (int e = 0; e < NEXP; e++) s += expf(acc[e] - mx);
        g_prob[t] = 1.0f / s;
        int slot = atomicAdd(&g_count[mi], 1);
        g_bucket[mi * TOKENS + slot] = t;
        if (has_logits) {
            float* lg = dout + (size_t)TOKENS * DDIM + (size_t)t * NEXP;
#pragma unroll
            for (int e = 0; e < NEXP; e++) lg[e] = acc[e];
        }
        if (has_index)
            dout[(size_t)TOKENS * DDIM + (size_t)TOKENS * NEXP + t] = (float)mi;
    }
}

// Transpose + split: in fp32 [E][R][C] -> bf16 hi/lo [E][C][R].
// W1SEL selects the OUTPUT device globals INSIDE device code — a __device__
// symbol must never be passed as a host-side kernel argument (on GB300/ATS the
// host shadow address is silently writable: R3/R4 root cause).
template<bool W1SEL, int R, int C>
__global__ void transpose_split(const float* __restrict__ in) {
    __nv_bfloat16* __restrict__ ohi = W1SEL ? g_w1t_hi : g_w2t_hi;
    __nv_bfloat16* __restrict__ olo = W1SEL ? g_w1t_lo : g_w2t_lo;
    __shared__ float s[64][65];
    const int e = blockIdx.z;
    const float* I = in + (size_t)e * R * C;
    const size_t obase = (size_t)e * R * C;
    const int r0 = blockIdx.y * 64, c0 = blockIdx.x * 64;
    const int tid = threadIdx.x;
#pragma unroll
    for (int i = 0; i < 16; i++) {
        int idx = tid + i * 256;
        int rr = idx >> 6, cc = idx & 63;
        s[rr][cc] = I[(size_t)(r0 + rr) * C + c0 + cc];
    }
    __syncthreads();
#pragma unroll
    for (int i = 0; i < 8; i++) {
        int idx = tid + i * 256;
        int oc = idx >> 5, rp = idx & 31;
        float v0 = s[rp * 2][oc], v1 = s[rp * 2 + 1][oc];
        uint32_t hw = bf16hi2(v0, v1);
        uint32_t lw = bf16hi2(bf16res(v0), bf16res(v1));
        size_t o = obase + (size_t)(c0 + oc) * R + r0 + rp * 2;
        ((uint32_t*)ohi)[o >> 1] = hw;
        ((uint32_t*)olo)[o >> 1] = lw;
    }
}

// ---------------- mma.sync gather-GEMM (128x128 tile, bf16 3-product split)
// FIRST:  h1[tok] = relu(x[tok] @ w1[e] + b1[e])      (fp32, to g_h1)
// !FIRST: out[tok] = (h1[tok] @ w2[e] + b2[e]) * prob[tok]
// D[m,n] = sum_k A[m,k]*B[n,k]; A fp32 source (split in-register), B pre-split.
template<bool FIRST, int KD, int ND>
__global__ __launch_bounds__(256, 2)
void moe_mma(const float* __restrict__ Asrc,
             const float* __restrict__ bias,
             float* __restrict__ Cout) {
    constexpr int NCH = KD / 16;                 // 16-wide K chunks
    constexpr uint32_t PLANE = 4096;             // 128 rows * 32 bytes
    constexpr uint32_t A_HI = 0, A_LO = PLANE, B_HI = 2 * PLANE, B_LO = 3 * PLANE;
    constexpr uint32_t BUF = 4 * PLANE;          // 16384 per stage

    __shared__ __align__(16) char sbuf[2 * BUF]; // 32 KB static
    __shared__ int stok[128];

    const int e = blockIdx.z;
    const int cnt = g_count[e];
    const int row0 = blockIdx.y * 128;
    if (row0 >= cnt) return;
    const int col0 = blockIdx.x * 128;
    const int tid = threadIdx.x;

    for (int i = tid; i < 128; i += 256) {
        int r = row0 + i;
        stok[i] = (r < cnt) ? g_bucket[e * TOKENS + r] : -1;
    }
    __syncthreads();

    const uint32_t sb = smem_to_u32(sbuf);

    // ---- loader setup: thread handles tile-row tid>>1, 16B k-unit tid&1 ----
    const int lrow = tid >> 1, half = tid & 1;
    const int tok = stok[lrow];
    const int tokc = tok < 0 ? 0 : tok;

    const float* aS = (FIRST ? Asrc : g_h1) + (size_t)tokc * KD + half * 8;
    const __nv_bfloat16* wHp =
        (FIRST ? g_w1t_hi : g_w2t_hi) + ((size_t)e * ND + col0 + lrow) * KD + half * 8;
    const __nv_bfloat16* wLp =
        (FIRST ? g_w1t_lo : g_w2t_lo) + ((size_t)e * ND + col0 + lrow) * KD + half * 8;
    const uint32_t dsw = sw((uint32_t)lrow, (uint32_t)half);

    auto issue = [&](int c) {
        const uint32_t bb = sb + (uint32_t)(c & 1) * BUF;
        const int kk = c * 16;
        CP16(bb + B_HI + dsw, wHp + kk);
        CP16(bb + B_LO + dsw, wLp + kk);
        float4 v0 = *(const float4*)(aS + kk);
        float4 v1 = *(const float4*)(aS + kk + 4);
        STS128(bf16hi2(v0.x, v0.y), bf16hi2(v0.z, v0.w),
               bf16hi2(v1.x, v1.y), bf16hi2(v1.z, v1.w), bb + A_HI + dsw);
        STS128(bf16hi2(bf16res(v0.x), bf16res(v0.y)),
               bf16hi2(bf16res(v0.z), bf16res(v0.w)),
               bf16hi2(bf16res(v1.x), bf16res(v1.y)),
               bf16hi2(bf16res(v1.z), bf16res(v1.w)), bb + A_LO + dsw);
        asm volatile("cp.async.commit_group;" ::: "memory");
    };

    // ---- compute setup: 8 warps = 4(M) x 2(N); warp tile 32x64 -------------
    const int w = tid >> 5, l = tid & 31;
    const int m0 = (w & 3) * 32;
    const int n0w = (w >> 2) * 64;
    float acc[2][8][4];
#pragma unroll
    for (int i = 0; i < 2; i++)
#pragma unroll
        for (int j = 0; j < 8; j++)
#pragma unroll
            for (int q = 0; q < 4; q++) acc[i][j][q] = 0.f;

    auto compute = [&](int c) {
        const uint32_t bb = sb + (uint32_t)(c & 1) * BUF;
        uint32_t aH[2][4], aL[2][4];
#pragma unroll
        for (int i = 0; i < 2; i++) {
            uint32_t ra = bb + sw((uint32_t)(m0 + i * 16 + (l & 15)),
                                  (uint32_t)(l >> 4));
            LDSM4(aH[i], ra + A_HI);
            LDSM4(aL[i], ra + A_LO);
        }
#pragma unroll
        for (int jj = 0; jj < 4; jj++) {
            uint32_t rb = bb + sw((uint32_t)(n0w + jj * 16 + (l & 7) + ((l >> 4) << 3)),
                                  (uint32_t)((l >> 3) & 1));
            uint32_t tH[4], tL[4];
            LDSM4(tH, rb + B_HI);
            LDSM4(tL, rb + B_LO);
#pragma unroll
            for (int i = 0; i < 2; i++) {
                MMA(acc[i][2 * jj],     aH[i], tH[0], tH[1]);
                MMA(acc[i][2 * jj],     aH[i], tL[0], tL[1]);
                MMA(acc[i][2 * jj],     aL[i], tH[0], tH[1]);
                MMA(acc[i][2 * jj + 1], aH[i], tH[2], tH[3]);
                MMA(acc[i][2 * jj + 1], aH[i], tL[2], tL[3]);
                MMA(acc[i][2 * jj + 1], aL[i], tH[2], tH[3]);
            }
        }
    };

    // ---- double-buffered pipeline ------------------------------------------
    issue(0);
    issue(1);
    for (int c = 0; c < NCH; c++) {
        if (c + 1 < NCH) {
            asm volatile("cp.async.wait_group 1;" ::: "memory");
        } else {
            asm volatile("cp.async.wait_group 0;" ::: "memory");
        }
        __syncthreads();
        compute(c);
        __syncthreads();
        if (c + 2 < NCH) issue(c + 2);
    }

    // ---- epilogue ----------------------------------------------------------
    const float* bptr = bias + (size_t)e * ND;
#pragma unroll
    for (int i = 0; i < 2; i++) {
#pragma unroll
        for (int h2 = 0; h2 < 2; h2++) {
            int mrow = m0 + i * 16 + (l >> 2) + h2 * 8;
            int t2 = stok[mrow];
            if (t2 < 0) continue;
            float p = FIRST ? 0.f : g_prob[t2];
#pragma unroll
            for (int j = 0; j < 8; j++) {
                int col = col0 + n0w + j * 8 + (l & 3) * 2;
                float v0 = acc[i][j][h2 * 2 + 0] + bptr[col];
                float v1 = acc[i][j][h2 * 2 + 1] + bptr[col + 1];
                if (FIRST) {
                    v0 = v0 > 0.f ? v0 : 0.f;
                    v1 = v1 > 0.f ? v1 : 0.f;
                    *(float2*)(g_h1 + (size_t)t2 * FDIM + col) = make_float2(v0, v1);
                } else {
                    *(float2*)(Cout + (size_t)t2 * DDIM + col) =
                        make_float2(v0 * p, v1 * p);
                }
            }
        }
    }
}

// ---------------- launch ----------------------------------------------------
extern "C" void kernel_launch(void* const* d_in, const int* in_sizes, int n_in,
                              void* d_out, int out_size) {
    const float* x  = (const float*)d_in[0];   // [4,1024,768]
    const float* wr = (const float*)d_in[1];   // [768,8]
    const float* w1 = (const float*)d_in[2];   // [8,768,3072]
    const float* b1 = (const float*)d_in[3];   // [8,3072]
    const float* w2 = (const float*)d_in[4];   // [8,3072,768]
    const float* b2 = (const float*)d_in[5];   // [8,768]
    float* out = (float*)d_out;

    const int hid = TOKENS * DDIM;
    int has_logits = (out_size >= hid + TOKENS * NEXP) ? 1 : 0;
    int has_index  = (out_size >= hid + TOKENS * NEXP + TOKENS) ? 1 : 0;

    reset_kernel<<<1, 32>>>();
    router_kernel<<<TOKENS / 8, 256>>>(x, wr, out, has_logits, has_index);

    // outputs selected inside device code (device globals; see comment above)
    transpose_split<true,  DDIM, FDIM>
        <<<dim3(FDIM / 64, DDIM / 64, NEXP), 256>>>(w1);
    transpose_split<false, FDIM, DDIM>
        <<<dim3(DDIM / 64, FDIM / 64, NEXP), 256>>>(w2);

    // GEMM1: [cnt x 768] @ w1 -> relu -> g_h1 (fp32)
    moe_mma<true, DDIM, FDIM>
        <<<dim3(FDIM / 128, TOKENS / 128, NEXP), 256>>>(x, b1, nullptr);
    // GEMM2: [cnt x 3072] @ w2 -> +bias, *prob -> out
    moe_mma<false, FDIM, DDIM>
        <<<dim3(DDIM / 128, TOKENS / 128, NEXP), 256>>>(nullptr, b2, out);
}

// round 7
// speedup vs baseline: 2.1744x; 1.0448x over previous
#include <cuda_runtime.h>
#include <cuda_bf16.h>
#include <cstdint>

#define TOKENS 4096
#define DDIM 768
#define FDIM 3072
#define NEXP 8

// ---------------- scratch (__device__ globals; no allocs allowed) ----------
__device__ __nv_bfloat16 g_h1_hi[(size_t)TOKENS * FDIM];  // split h1 planes
__device__ __nv_bfloat16 g_h1_lo[(size_t)TOKENS * FDIM];
__device__ float g_prob[TOKENS];
__device__ int   g_bucket[NEXP * TOKENS];
__device__ int   g_count[NEXP];
__device__ __nv_bfloat16 g_w1t_hi[(size_t)NEXP * FDIM * DDIM];  // [e][f][d]
__device__ __nv_bfloat16 g_w1t_lo[(size_t)NEXP * FDIM * DDIM];
__device__ __nv_bfloat16 g_w2t_hi[(size_t)NEXP * DDIM * FDIM];  // [e][d][f]
__device__ __nv_bfloat16 g_w2t_lo[(size_t)NEXP * DDIM * FDIM];

// ---------------- PTX helpers (baseline ISA only) ---------------------------
__device__ __forceinline__ uint32_t smem_to_u32(const void* p) {
    uint32_t a;
    asm("{ .reg .u64 t; cvta.to.shared.u64 t, %1; cvt.u32.u64 %0, t; }"
        : "=r"(a) : "l"(p));
    return a;
}

#define CP16(dst, src) \
    asm volatile("cp.async.cg.shared.global [%0], [%1], 16;" \
                 :: "r"(dst), "l"(src) : "memory")

#define STS128(r0, r1, r2, r3, smem_addr) \
    asm volatile("st.shared.v4.b32 [%0], {%1, %2, %3, %4};" \
                 :: "r"(smem_addr), "r"(r0), "r"(r1), "r"(r2), "r"(r3) : "memory")

#define LDSM4(r, addr) \
    asm volatile("ldmatrix.sync.aligned.m8n8.x4.shared.b16 {%0,%1,%2,%3}, [%4];" \
                 : "=r"((r)[0]), "=r"((r)[1]), "=r"((r)[2]), "=r"((r)[3]) \
                 : "r"(addr))

#define MMA(c, a, b0, b1) \
    asm volatile("mma.sync.aligned.m16n8k16.row.col.f32.bf16.bf16.f32 " \
                 "{%0,%1,%2,%3}, {%4,%5,%6,%7}, {%8,%9}, {%0,%1,%2,%3};" \
                 : "+f"((c)[0]), "+f"((c)[1]), "+f"((c)[2]), "+f"((c)[3]) \
                 : "r"((a)[0]), "r"((a)[1]), "r"((a)[2]), "r"((a)[3]), \
                   "r"(b0), "r"(b1))

// bf16 split helpers: value = hi + lo, hi = bf16(v), lo = bf16(v - hi)
__device__ __forceinline__ uint32_t bf16hi2(float a, float b) {
    return (uint32_t)__bfloat16_as_ushort(__float2bfloat16(a)) |
           ((uint32_t)__bfloat16_as_ushort(__float2bfloat16(b)) << 16);
}
__device__ __forceinline__ float bf16res(float a) {
    return a - __bfloat162float(__float2bfloat16(a));
}

// swizzled byte offset: 64B rows, 16B unit u in 0..3, conflict-free XOR
__device__ __forceinline__ uint32_t sw64(uint32_t row, uint32_t u) {
    return row * 64 + ((u ^ (row >> 1)) & 3u) * 16;
}

// ---------------- small kernels --------------------------------------------
__global__ void reset_kernel() {
    if (threadIdx.x < NEXP) g_count[threadIdx.x] = 0;
}

__global__ void router_kernel(const float* __restrict__ x,
                              const float* __restrict__ wr,
                              float* __restrict__ dout,
                              int has_logits, int has_index) {
    int warp = threadIdx.x >> 5, lane = threadIdx.x & 31;
    int t = blockIdx.x * 8 + warp;
    if (t >= TOKENS) return;
    float acc[NEXP];
#pragma unroll
    for (int e = 0; e < NEXP; e++) acc[e] = 0.f;
    const float* xr = x + (size_t)t * DDIM;
    for (int d = lane; d < DDIM; d += 32) {
        float xv = xr[d];
#pragma unroll
        for (int e = 0; e < NEXP; e++) acc[e] += xv * wr[d * NEXP + e];
    }
#pragma unroll
    for (int e = 0; e < NEXP; e++) {
#pragma unroll
        for (int o = 16; o; o >>= 1)
            acc[e] += __shfl_xor_sync(0xffffffffu, acc[e], o);
    }
    if (lane == 0) {
        float mx = acc[0]; int mi = 0;
#pragma unroll
        for (int e = 1; e < NEXP; e++)
            if (acc[e] > mx) { mx = acc[e]; mi = e; }
        float s = 0.f;
#pragma unroll
        for (int e = 0; e < NEXP; e++) s += expf(acc[e] - mx);
        g_prob[t] = 1.0f / s;
        int slot = atomicAdd(&g_count[mi], 1);
        g_bucket[mi * TOKENS + slot] = t;
        if (has_logits) {
            float* lg = dout + (size_t)TOKENS * DDIM + (size_t)t * NEXP;
#pragma unroll
            for (int e = 0; e < NEXP; e++) lg[e] = acc[e];
        }
        if (has_index)
            dout[(size_t)TOKENS * DDIM + (size_t)TOKENS * NEXP + t] = (float)mi;
    }
}

// Transpose + split: in fp32 [E][R][C] -> bf16 hi/lo [E][C][R].
// Output globals selected INSIDE device code (never pass __device__ symbols
// from host — GB300 ATS makes the host shadow silently writable).
template<bool W1SEL, int R, int C>
__global__ void transpose_split(const float* __restrict__ in) {
    __nv_bfloat16* __restrict__ ohi = W1SEL ? g_w1t_hi : g_w2t_hi;
    __nv_bfloat16* __restrict__ olo = W1SEL ? g_w1t_lo : g_w2t_lo;
    __shared__ float s[64][65];
    const int e = blockIdx.z;
    const float* I = in + (size_t)e * R * C;
    const size_t obase = (size_t)e * R * C;
    const int r0 = blockIdx.y * 64, c0 = blockIdx.x * 64;
    const int tid = threadIdx.x;
#pragma unroll
    for (int i = 0; i < 16; i++) {
        int idx = tid + i * 256;
        int rr = idx >> 6, cc = idx & 63;
        s[rr][cc] = I[(size_t)(r0 + rr) * C + c0 + cc];
    }
    __syncthreads();
#pragma unroll
    for (int i = 0; i < 8; i++) {
        int idx = tid + i * 256;
        int oc = idx >> 5, rp = idx & 31;
        float v0 = s[rp * 2][oc], v1 = s[rp * 2 + 1][oc];
        uint32_t hw = bf16hi2(v0, v1);
        uint32_t lw = bf16hi2(bf16res(v0), bf16res(v1));
        size_t o = obase + (size_t)(c0 + oc) * R + r0 + rp * 2;
        ((uint32_t*)ohi)[o >> 1] = hw;
        ((uint32_t*)olo)[o >> 1] = lw;
    }
}

// ---------------- mma.sync gather-GEMM -------------------------------------
// 128x128 CTA tile, K-chunk 32, 3-stage cp.async ring, bf16 3-product split.
// FIRST:  h1[tok] = relu(x[tok] @ w1[e] + b1[e])  -> split hi/lo planes
// !FIRST: out[tok] = (h1[tok] @ w2[e] + b2[e]) * prob[tok]
template<bool FIRST, int KD, int ND>
__global__ __launch_bounds__(256, 2)
void moe_mma(const float* __restrict__ Asrc,
             const float* __restrict__ bias,
             float* __restrict__ Cout) {
    constexpr int NCH = KD / 32;                  // 32-wide K chunks
    constexpr uint32_t PLANE = 8192;              // 128 rows * 64 bytes
    constexpr uint32_t A_HI = 0, A_LO = PLANE, B_HI = 2 * PLANE, B_LO = 3 * PLANE;
    constexpr uint32_t STAGE = 4 * PLANE;         // 32 KB per stage, 3 stages

    extern __shared__ __align__(16) char sbuf[];
    __shared__ int stok[128];

    const int e = blockIdx.z;
    const int cnt = g_count[e];
    const int row0 = blockIdx.y * 128;
    if (row0 >= cnt) return;
    const int col0 = blockIdx.x * 128;
    const int tid = threadIdx.x;

    for (int i = tid; i < 128; i += 256) {
        int r = row0 + i;
        stok[i] = (r < cnt) ? g_bucket[e * TOKENS + r] : -1;
    }
    __syncthreads();

    const uint32_t sb = smem_to_u32(sbuf);

    // ---- loader: thread -> tile-row tid>>1, k-half (16 elems) tid&1 --------
    const int lrow = tid >> 1, half = tid & 1;
    const int tok = stok[lrow];
    const int tokc = tok < 0 ? 0 : tok;

    const float* aS = Asrc + (size_t)tokc * KD + half * 16;              // FIRST
    const __nv_bfloat16* aHp = g_h1_hi + (size_t)tokc * KD + half * 16;  // !FIRST
    const __nv_bfloat16* aLp = g_h1_lo + (size_t)tokc * KD + half * 16;
    const __nv_bfloat16* wHp =
        (FIRST ? g_w1t_hi : g_w2t_hi) + ((size_t)e * ND + col0 + lrow) * KD + half * 16;
    const __nv_bfloat16* wLp =
        (FIRST ? g_w1t_lo : g_w2t_lo) + ((size_t)e * ND + col0 + lrow) * KD + half * 16;
    const uint32_t d0 = sw64((uint32_t)lrow, (uint32_t)(half * 2));
    const uint32_t d1 = sw64((uint32_t)lrow, (uint32_t)(half * 2 + 1));

    auto issue = [&](int c) {
        const uint32_t bb = sb + (uint32_t)(c % 3) * STAGE;
        const int kk = c * 32;
        CP16(bb + B_HI + d0, wHp + kk);
        CP16(bb + B_HI + d1, wHp + kk + 8);
        CP16(bb + B_LO + d0, wLp + kk);
        CP16(bb + B_LO + d1, wLp + kk + 8);
        if (FIRST) {
            float4 v0 = *(const float4*)(aS + kk);
            float4 v1 = *(const float4*)(aS + kk + 4);
            float4 v2 = *(const float4*)(aS + kk + 8);
            float4 v3 = *(const float4*)(aS + kk + 12);
            STS128(bf16hi2(v0.x, v0.y), bf16hi2(v0.z, v0.w),
                   bf16hi2(v1.x, v1.y), bf16hi2(v1.z, v1.w), bb + A_HI + d0);
            STS128(bf16hi2(v2.x, v2.y), bf16hi2(v2.z, v2.w),
                   bf16hi2(v3.x, v3.y), bf16hi2(v3.z, v3.w), bb + A_HI + d1);
            STS128(bf16hi2(bf16res(v0.x), bf16res(v0.y)),
                   bf16hi2(bf16res(v0.z), bf16res(v0.w)),
                   bf16hi2(bf16res(v1.x), bf16res(v1.y)),
                   bf16hi2(bf16res(v1.z), bf16res(v1.w)), bb + A_LO + d0);
            STS128(bf16hi2(bf16res(v2.x), bf16res(v2.y)),
                   bf16hi2(bf16res(v2.z), bf16res(v2.w)),
                   bf16hi2(bf16res(v3.x), bf16res(v3.y)),
                   bf16hi2(bf16res(v3.z), bf16res(v3.w)), bb + A_LO + d1);
        } else {
            CP16(bb + A_HI + d0, aHp + kk);
            CP16(bb + A_HI + d1, aHp + kk + 8);
            CP16(bb + A_LO + d0, aLp + kk);
            CP16(bb + A_LO + d1, aLp + kk + 8);
        }
        asm volatile("cp.async.commit_group;" ::: "memory");
    };

    // ---- compute: 8 warps = 4(M) x 2(N); warp tile 32x64 -------------------
    const int w = tid >> 5, l = tid & 31;
    const int m0 = (w & 3) * 32;
    const int n0w = (w >> 2) * 64;
    float acc[2][8][4];
#pragma unroll
    for (int i = 0; i < 2; i++)
#pragma unroll
        for (int j = 0; j < 8; j++)
#pragma unroll
            for (int q = 0; q < 4; q++) acc[i][j][q] = 0.f;

    auto compute = [&](int c) {
        const uint32_t bb = sb + (uint32_t)(c % 3) * STAGE;
#pragma unroll
        for (int s = 0; s < 2; s++) {            // two k16 substeps of chunk
            uint32_t aH[2][4], aL[2][4];
#pragma unroll
            for (int i = 0; i < 2; i++) {
                uint32_t ra = bb + sw64((uint32_t)(m0 + i * 16 + (l & 15)),
                                        (uint32_t)(2 * s + (l >> 4)));
                LDSM4(aH[i], ra + A_HI);
                LDSM4(aL[i], ra + A_LO);
            }
#pragma unroll
            for (int jj = 0; jj < 4; jj++) {
                uint32_t rb = bb + sw64((uint32_t)(n0w + jj * 16 + (l & 7) + ((l >> 4) << 3)),
                                        (uint32_t)(2 * s + ((l >> 3) & 1)));
                uint32_t tH[4], tL[4];
                LDSM4(tH, rb + B_HI);
                LDSM4(tL, rb + B_LO);
#pragma unroll
                for (int i = 0; i < 2; i++) {
                    MMA(acc[i][2 * jj],     aH[i], tH[0], tH[1]);
                    MMA(acc[i][2 * jj],     aH[i], tL[0], tL[1]);
                    MMA(acc[i][2 * jj],     aL[i], tH[0], tH[1]);
                    MMA(acc[i][2 * jj + 1], aH[i], tH[2], tH[3]);
                    MMA(acc[i][2 * jj + 1], aH[i], tL[2], tL[3]);
                    MMA(acc[i][2 * jj + 1], aL[i], tH[2], tH[3]);
                }
            }
        }
    };

    // ---- 3-stage pipeline, prefetch issued right after wait ---------------
    issue(0);
    issue(1);
    for (int c = 0; c < NCH; c++) {
        if (c + 1 < NCH) {
            asm volatile("cp.async.wait_group 1;" ::: "memory");
        } else {
            asm volatile("cp.async.wait_group 0;" ::: "memory");
        }
        if (c + 2 < NCH) issue(c + 2);   // safe: all warps past iter c-1's 2nd bar
        __syncthreads();
        compute(c);
        __syncthreads();
    }

    // ---- epilogue ----------------------------------------------------------
    const float* bptr = bias + (size_t)e * ND;
#pragma unroll
    for (int i = 0; i < 2; i++) {
#pragma unroll
        for (int h2 = 0; h2 < 2; h2++) {
            int mrow = m0 + i * 16 + (l >> 2) + h2 * 8;
            int t2 = stok[mrow];
            if (t2 < 0) continue;
            float p = FIRST ? 0.f : g_prob[t2];
#pragma unroll
            for (int j = 0; j < 8; j++) {
                int col = col0 + n0w + j * 8 + (l & 3) * 2;
                float v0 = acc[i][j][h2 * 2 + 0] + bptr[col];
                float v1 = acc[i][j][h2 * 2 + 1] + bptr[col + 1];
                if (FIRST) {
                    v0 = v0 > 0.f ? v0 : 0.f;
                    v1 = v1 > 0.f ? v1 : 0.f;
                    *(uint32_t*)(g_h1_hi + (size_t)t2 * FDIM + col) = bf16hi2(v0, v1);
                    *(uint32_t*)(g_h1_lo + (size_t)t2 * FDIM + col) =
                        bf16hi2(bf16res(v0), bf16res(v1));
                } else {
                    *(float2*)(Cout + (size_t)t2 * DDIM + col) =
                        make_float2(v0 * p, v1 * p);
                }
            }
        }
    }
}

// ---------------- launch ----------------------------------------------------
extern "C" void kernel_launch(void* const* d_in, const int* in_sizes, int n_in,
                              void* d_out, int out_size) {
    const float* x  = (const float*)d_in[0];   // [4,1024,768]
    const float* wr = (const float*)d_in[1];   // [768,8]
    const float* w1 = (const float*)d_in[2];   // [8,768,3072]
    const float* b1 = (const float*)d_in[3];   // [8,3072]
    const float* w2 = (const float*)d_in[4];   // [8,3072,768]
    const float* b2 = (const float*)d_in[5];   // [8,768]
    float* out = (float*)d_out;

    const int hid = TOKENS * DDIM;
    int has_logits = (out_size >= hid + TOKENS * NEXP) ? 1 : 0;
    int has_index  = (out_size >= hid + TOKENS * NEXP + TOKENS) ? 1 : 0;

    const int SMEM_BYTES = 3 * 32768;   // 96 KB dynamic (3-stage ring)
    cudaFuncSetAttribute(moe_mma<true, DDIM, FDIM>,
                         cudaFuncAttributeMaxDynamicSharedMemorySize, SMEM_BYTES);
    cudaFuncSetAttribute(moe_mma<false, FDIM, DDIM>,
                         cudaFuncAttributeMaxDynamicSharedMemorySize, SMEM_BYTES);

    reset_kernel<<<1, 32>>>();
    router_kernel<<<TOKENS / 8, 256>>>(x, wr, out, has_logits, has_index);

    transpose_split<true,  DDIM, FDIM>
        <<<dim3(FDIM / 64, DDIM / 64, NEXP), 256>>>(w1);
    transpose_split<false, FDIM, DDIM>
        <<<dim3(DDIM / 64, FDIM / 64, NEXP), 256>>>(w2);

    // GEMM1: [cnt x 768] @ w1 -> relu -> split h1 planes
    moe_mma<true, DDIM, FDIM>
        <<<dim3(FDIM / 128, TOKENS / 128, NEXP), 256, SMEM_BYTES>>>(x, b1, nullptr);
    // GEMM2: [cnt x 3072] @ w2 -> +bias, *prob -> out
    moe_mma<false, FDIM, DDIM>
        <<<dim3(DDIM / 128, TOKENS / 128, NEXP), 256, SMEM_BYTES>>>(nullptr, b2, out);
}

// round 8
// speedup vs baseline: 2.8232x; 1.2984x over previous
#include <cuda_runtime.h>
#include <cuda_bf16.h>
#include <cuda_fp16.h>
#include <cstdint>

#define TOKENS 4096
#define DDIM 768
#define FDIM 3072
#define NEXP 8

// ---------------- scratch (__device__ globals; no allocs allowed) ----------
__device__ __half g_h1_hi[(size_t)TOKENS * FDIM];   // split h1 planes (fp16)
__device__ __half g_h1_lo[(size_t)TOKENS * FDIM];
__device__ float g_prob[TOKENS];
__device__ int   g_bucket[NEXP * TOKENS];
__device__ int   g_count[NEXP];
__device__ __half g_w1t[(size_t)NEXP * FDIM * DDIM];  // [e][f][d] single plane
__device__ __half g_w2t[(size_t)NEXP * DDIM * FDIM];  // [e][d][f]

// ---------------- PTX helpers (baseline ISA only) ---------------------------
__device__ __forceinline__ uint32_t smem_to_u32(const void* p) {
    uint32_t a;
    asm("{ .reg .u64 t; cvta.to.shared.u64 t, %1; cvt.u32.u64 %0, t; }"
        : "=r"(a) : "l"(p));
    return a;
}

#define CP16(dst, src) \
    asm volatile("cp.async.cg.shared.global [%0], [%1], 16;" \
                 :: "r"(dst), "l"(src) : "memory")

#define STS128(r0, r1, r2, r3, smem_addr) \
    asm volatile("st.shared.v4.b32 [%0], {%1, %2, %3, %4};" \
                 :: "r"(smem_addr), "r"(r0), "r"(r1), "r"(r2), "r"(r3) : "memory")

#define LDSM4(r, addr) \
    asm volatile("ldmatrix.sync.aligned.m8n8.x4.shared.b16 {%0,%1,%2,%3}, [%4];" \
                 : "=r"((r)[0]), "=r"((r)[1]), "=r"((r)[2]), "=r"((r)[3]) \
                 : "r"(addr))

#define MMA(c, a, b0, b1) \
    asm volatile("mma.sync.aligned.m16n8k16.row.col.f32.f16.f16.f32 " \
                 "{%0,%1,%2,%3}, {%4,%5,%6,%7}, {%8,%9}, {%0,%1,%2,%3};" \
                 : "+f"((c)[0]), "+f"((c)[1]), "+f"((c)[2]), "+f"((c)[3]) \
                 : "r"((a)[0]), "r"((a)[1]), "r"((a)[2]), "r"((a)[3]), \
                   "r"(b0), "r"(b1))

// fp16 split helpers: value = hi + lo, hi = fp16(v), lo = fp16(v - hi)
__device__ __forceinline__ uint32_t h2pack(float a, float b) {
    __half2 h = __floats2half2_rn(a, b);
    return *(uint32_t*)&h;
}
__device__ __forceinline__ float h16res(float a) {
    return a - __half2float(__float2half_rn(a));
}

// swizzled byte offset: 64B rows, 16B unit u in 0..3, conflict-free XOR
__device__ __forceinline__ uint32_t sw64(uint32_t row, uint32_t u) {
    return row * 64 + ((u ^ (row >> 1)) & 3u) * 16;
}

// ---------------- small kernels --------------------------------------------
__global__ void reset_kernel() {
    if (threadIdx.x < NEXP) g_count[threadIdx.x] = 0;
}

__global__ void router_kernel(const float* __restrict__ x,
                              const float* __restrict__ wr,
                              float* __restrict__ dout,
                              int has_logits, int has_index) {
    int warp = threadIdx.x >> 5, lane = threadIdx.x & 31;
    int t = blockIdx.x * 8 + warp;
    if (t >= TOKENS) return;
    float acc[NEXP];
#pragma unroll
    for (int e = 0; e < NEXP; e++) acc[e] = 0.f;
    const float* xr = x + (size_t)t * DDIM;
    for (int d = lane; d < DDIM; d += 32) {
        float xv = xr[d];
#pragma unroll
        for (int e = 0; e < NEXP; e++) acc[e] += xv * wr[d * NEXP + e];
    }
#pragma unroll
    for (int e = 0; e < NEXP; e++) {
#pragma unroll
        for (int o = 16; o; o >>= 1)
            acc[e] += __shfl_xor_sync(0xffffffffu, acc[e], o);
    }
    if (lane == 0) {
        float mx = acc[0]; int mi = 0;
#pragma unroll
        for (int e = 1; e < NEXP; e++)
            if (acc[e] > mx) { mx = acc[e]; mi = e; }
        float s = 0.f;
#pragma unroll
        for (int e = 0; e < NEXP; e++) s += expf(acc[e] - mx);
        g_prob[t] = 1.0f / s;
        int slot = atomicAdd(&g_count[mi], 1);
        g_bucket[mi * TOKENS + slot] = t;
        if (has_logits) {
            float* lg = dout + (size_t)TOKENS * DDIM + (size_t)t * NEXP;
#pragma unroll
            for (int e = 0; e < NEXP; e++) lg[e] = acc[e];
        }
        if (has_index)
            dout[(size_t)TOKENS * DDIM + (size_t)TOKENS * NEXP + t] = (float)mi;
    }
}

// Transpose: in fp32 [E][R][C] -> fp16 [E][C][R] (single plane).
// Output globals selected INSIDE device code (never pass __device__ symbols
// from host — GB300 ATS makes the host shadow silently writable).
template<bool W1SEL, int R, int C>
__global__ void transpose_h16(const float* __restrict__ in) {
    __half* __restrict__ o16 = W1SEL ? g_w1t : g_w2t;
    __shared__ float s[64][65];
    const int e = blockIdx.z;
    const float* I = in + (size_t)e * R * C;
    const size_t obase = (size_t)e * R * C;
    const int r0 = blockIdx.y * 64, c0 = blockIdx.x * 64;
    const int tid = threadIdx.x;
#pragma unroll
    for (int i = 0; i < 16; i++) {
        int idx = tid + i * 256;
        int rr = idx >> 6, cc = idx & 63;
        s[rr][cc] = I[(size_t)(r0 + rr) * C + c0 + cc];
    }
    __syncthreads();
#pragma unroll
    for (int i = 0; i < 8; i++) {
        int idx = tid + i * 256;
        int oc = idx >> 5, rp = idx & 31;
        float v0 = s[rp * 2][oc], v1 = s[rp * 2 + 1][oc];
        size_t o = obase + (size_t)(c0 + oc) * R + r0 + rp * 2;
        ((uint32_t*)o16)[o >> 1] = h2pack(v0, v1);
    }
}

// ---------------- mma.sync gather-GEMM -------------------------------------
// 128x128 CTA tile, K-chunk 32, 3-stage cp.async ring.
// Asymmetric fp16 2-product split: A = a_hi + a_lo (exact to 2^-22),
// B = fp16(w) single plane; D = a_hi*b + a_lo*b. Error ~= B rounding only.
// FIRST:  h1[tok] = relu(x[tok] @ w1[e] + b1[e])  -> split hi/lo planes
// !FIRST: out[tok] = (h1[tok] @ w2[e] + b2[e]) * prob[tok]
template<bool FIRST, int KD, int ND>
__global__ __launch_bounds__(256, 2)
void moe_mma(const float* __restrict__ Asrc,
             const float* __restrict__ bias,
             float* __restrict__ Cout) {
    constexpr int NCH = KD / 32;                  // 32-wide K chunks
    constexpr uint32_t PLANE = 8192;              // 128 rows * 64 bytes
    constexpr uint32_t A_HI = 0, A_LO = PLANE, B_PL = 2 * PLANE;
    constexpr uint32_t STAGE = 3 * PLANE;         // 24 KB per stage, 3 stages

    extern __shared__ __align__(16) char sbuf[];
    __shared__ int stok[128];

    const int e = blockIdx.z;
    const int cnt = g_count[e];
    const int row0 = blockIdx.y * 128;
    if (row0 >= cnt) return;
    const int col0 = blockIdx.x * 128;
    const int tid = threadIdx.x;

    for (int i = tid; i < 128; i += 256) {
        int r = row0 + i;
        stok[i] = (r < cnt) ? g_bucket[e * TOKENS + r] : -1;
    }
    __syncthreads();

    const uint32_t sb = smem_to_u32(sbuf);

    // ---- loader: thread -> tile-row tid>>1, k-half (16 elems) tid&1 --------
    const int lrow = tid >> 1, half = tid & 1;
    const int tok = stok[lrow];
    const int tokc = tok < 0 ? 0 : tok;

    const float* aS = Asrc + (size_t)tokc * KD + half * 16;         // FIRST
    const __half* aHp = g_h1_hi + (size_t)tokc * KD + half * 16;    // !FIRST
    const __half* aLp = g_h1_lo + (size_t)tokc * KD + half * 16;
    const __half* wp =
        (FIRST ? g_w1t : g_w2t) + ((size_t)e * ND + col0 + lrow) * KD + half * 16;
    const uint32_t d0 = sw64((uint32_t)lrow, (uint32_t)(half * 2));
    const uint32_t d1 = sw64((uint32_t)lrow, (uint32_t)(half * 2 + 1));

    auto issue = [&](int c) {
        const uint32_t bb = sb + (uint32_t)(c % 3) * STAGE;
        const int kk = c * 32;
        CP16(bb + B_PL + d0, wp + kk);
        CP16(bb + B_PL + d1, wp + kk + 8);
        if (FIRST) {
            float4 v0 = *(const float4*)(aS + kk);
            float4 v1 = *(const float4*)(aS + kk + 4);
            float4 v2 = *(const float4*)(aS + kk + 8);
            float4 v3 = *(const float4*)(aS + kk + 12);
            STS128(h2pack(v0.x, v0.y), h2pack(v0.z, v0.w),
                   h2pack(v1.x, v1.y), h2pack(v1.z, v1.w), bb + A_HI + d0);
            STS128(h2pack(v2.x, v2.y), h2pack(v2.z, v2.w),
                   h2pack(v3.x, v3.y), h2pack(v3.z, v3.w), bb + A_HI + d1);
            STS128(h2pack(h16res(v0.x), h16res(v0.y)),
                   h2pack(h16res(v0.z), h16res(v0.w)),
                   h2pack(h16res(v1.x), h16res(v1.y)),
                   h2pack(h16res(v1.z), h16res(v1.w)), bb + A_LO + d0);
            STS128(h2pack(h16res(v2.x), h16res(v2.y)),
                   h2pack(h16res(v2.z), h16res(v2.w)),
                   h2pack(h16res(v3.x), h16res(v3.y)),
                   h2pack(h16res(v3.z), h16res(v3.w)), bb + A_LO + d1);
        } else {
            CP16(bb + A_HI + d0, aHp + kk);
            CP16(bb + A_HI + d1, aHp + kk + 8);
            CP16(bb + A_LO + d0, aLp + kk);
            CP16(bb + A_LO + d1, aLp + kk + 8);
        }
        asm volatile("cp.async.commit_group;" ::: "memory");
    };

    // ---- compute: 8 warps = 4(M) x 2(N); warp tile 32x64 -------------------
    const int w = tid >> 5, l = tid & 31;
    const int m0 = (w & 3) * 32;
    const int n0w = (w >> 2) * 64;
    float acc[2][8][4];
#pragma unroll
    for (int i = 0; i < 2; i++)
#pragma unroll
        for (int j = 0; j < 8; j++)
#pragma unroll
            for (int q = 0; q < 4; q++) acc[i][j][q] = 0.f;

    auto compute = [&](int c) {
        const uint32_t bb = sb + (uint32_t)(c % 3) * STAGE;
#pragma unroll
        for (int s = 0; s < 2; s++) {            // two k16 substeps of chunk
            uint32_t aH[2][4], aL[2][4];
#pragma unroll
            for (int i = 0; i < 2; i++) {
                uint32_t ra = bb + sw64((uint32_t)(m0 + i * 16 + (l & 15)),
                                        (uint32_t)(2 * s + (l >> 4)));
                LDSM4(aH[i], ra + A_HI);
                LDSM4(aL[i], ra + A_LO);
            }
#pragma unroll
            for (int jj = 0; jj < 4; jj++) {
                uint32_t rb = bb + sw64((uint32_t)(n0w + jj * 16 + (l & 7) + ((l >> 4) << 3)),
                                        (uint32_t)(2 * s + ((l >> 3) & 1)));
                uint32_t tB[4];
                LDSM4(tB, rb + B_PL);
#pragma unroll
                for (int i = 0; i < 2; i++) {
                    MMA(acc[i][2 * jj],     aH[i], tB[0], tB[1]);
                    MMA(acc[i][2 * jj],     aL[i], tB[0], tB[1]);
                    MMA(acc[i][2 * jj + 1], aH[i], tB[2], tB[3]);
                    MMA(acc[i][2 * jj + 1], aL[i], tB[2], tB[3]);
                }
            }
        }
    };

    // ---- 3-stage pipeline, prefetch issued right after wait ---------------
    issue(0);
    issue(1);
    for (int c = 0; c < NCH; c++) {
        if (c + 1 < NCH) {
            asm volatile("cp.async.wait_group 1;" ::: "memory");
        } else {
            asm volatile("cp.async.wait_group 0;" ::: "memory");
        }
        if (c + 2 < NCH) issue(c + 2);   // safe: all warps past iter c-1's 2nd bar
        __syncthreads();
        compute(c);
        __syncthreads();
    }

    // ---- epilogue ----------------------------------------------------------
    const float* bptr = bias + (size_t)e * ND;
#pragma unroll
    for (int i = 0; i < 2; i++) {
#pragma unroll
        for (int h2 = 0; h2 < 2; h2++) {
            int mrow = m0 + i * 16 + (l >> 2) + h2 * 8;
            int t2 = stok[mrow];
            if (t2 < 0) continue;
            float p = FIRST ? 0.f : g_prob[t2];
#pragma unroll
            for (int j = 0; j < 8; j++) {
                int col = col0 + n0w + j * 8 + (l & 3) * 2;
                float v0 = acc[i][j][h2 * 2 + 0] + bptr[col];
                float v1 = acc[i][j][h2 * 2 + 1] + bptr[col + 1];
                if (FIRST) {
                    v0 = v0 > 0.f ? v0 : 0.f;
                    v1 = v1 > 0.f ? v1 : 0.f;
                    *(uint32_t*)(g_h1_hi + (size_t)t2 * FDIM + col) = h2pack(v0, v1);
                    *(uint32_t*)(g_h1_lo + (size_t)t2 * FDIM + col) =
                        h2pack(h16res(v0), h16res(v1));
                } else {
                    *(float2*)(Cout + (size_t)t2 * DDIM + col) =
                        make_float2(v0 * p, v1 * p);
                }
            }
        }
    }
}

// ---------------- launch ----------------------------------------------------
extern "C" void kernel_launch(void* const* d_in, const int* in_sizes, int n_in,
                              void* d_out, int out_size) {
    const float* x  = (const float*)d_in[0];   // [4,1024,768]
    const float* wr = (const float*)d_in[1];   // [768,8]
    const float* w1 = (const float*)d_in[2];   // [8,768,3072]
    const float* b1 = (const float*)d_in[3];   // [8,3072]
    const float* w2 = (const float*)d_in[4];   // [8,3072,768]
    const float* b2 = (const float*)d_in[5];   // [8,768]
    float* out = (float*)d_out;

    const int hid = TOKENS * DDIM;
    int has_logits = (out_size >= hid + TOKENS * NEXP) ? 1 : 0;
    int has_index  = (out_size >= hid + TOKENS * NEXP + TOKENS) ? 1 : 0;

    const int SMEM_BYTES = 3 * 24576;   // 72 KB dynamic (3-stage ring)
    cudaFuncSetAttribute(moe_mma<true, DDIM, FDIM>,
                         cudaFuncAttributeMaxDynamicSharedMemorySize, SMEM_BYTES);
    cudaFuncSetAttribute(moe_mma<false, FDIM, DDIM>,
                         cudaFuncAttributeMaxDynamicSharedMemorySize, SMEM_BYTES);

    reset_kernel<<<1, 32>>>();
    router_kernel<<<TOKENS / 8, 256>>>(x, wr, out, has_logits, has_index);

    transpose_h16<true,  DDIM, FDIM>
        <<<dim3(FDIM / 64, DDIM / 64, NEXP), 256>>>(w1);
    transpose_h16<false, FDIM, DDIM>
        <<<dim3(DDIM / 64, FDIM / 64, NEXP), 256>>>(w2);

    // GEMM1: [cnt x 768] @ w1 -> relu -> split h1 planes
    moe_mma<true, DDIM, FDIM>
        <<<dim3(FDIM / 128, TOKENS / 128, NEXP), 256, SMEM_BYTES>>>(x, b1, nullptr);
    // GEMM2: [cnt x 3072] @ w2 -> +bias, *prob -> out
    moe_mma<false, FDIM, DDIM>
        <<<dim3(DDIM / 128, TOKENS / 128, NEXP), 256, SMEM_BYTES>>>(nullptr, b2, out);
}

// round 9
// speedup vs baseline: 3.7067x; 1.3129x over previous
#include <cuda_runtime.h>
#include <cuda_bf16.h>
#include <cuda_fp16.h>
#include <cstdint>

#define TOKENS 4096
#define DDIM 768
#define FDIM 3072
#define NEXP 8

// ---------------- scratch (__device__ globals; no allocs allowed) ----------
__device__ __half g_h1[(size_t)TOKENS * FDIM];      // fp16 intermediate
__device__ float g_prob[TOKENS];
__device__ int   g_bucket[NEXP * TOKENS];
__device__ int   g_count[NEXP];
__device__ __half g_w1t[(size_t)NEXP * FDIM * DDIM];  // [e][f][d]
__device__ __half g_w2t[(size_t)NEXP * DDIM * FDIM];  // [e][d][f]

// ---------------- PTX helpers (baseline ISA only) ---------------------------
__device__ __forceinline__ uint32_t smem_to_u32(const void* p) {
    uint32_t a;
    asm("{ .reg .u64 t; cvta.to.shared.u64 t, %1; cvt.u32.u64 %0, t; }"
        : "=r"(a) : "l"(p));
    return a;
}

#define CP16(dst, src) \
    asm volatile("cp.async.cg.shared.global [%0], [%1], 16;" \
                 :: "r"(dst), "l"(src) : "memory")

#define STS128(r0, r1, r2, r3, smem_addr) \
    asm volatile("st.shared.v4.b32 [%0], {%1, %2, %3, %4};" \
                 :: "r"(smem_addr), "r"(r0), "r"(r1), "r"(r2), "r"(r3) : "memory")

#define LDSM4(r, addr) \
    asm volatile("ldmatrix.sync.aligned.m8n8.x4.shared.b16 {%0,%1,%2,%3}, [%4];" \
                 : "=r"((r)[0]), "=r"((r)[1]), "=r"((r)[2]), "=r"((r)[3]) \
                 : "r"(addr))

#define MMA(c, a, b0, b1) \
    asm volatile("mma.sync.aligned.m16n8k16.row.col.f32.f16.f16.f32 " \
                 "{%0,%1,%2,%3}, {%4,%5,%6,%7}, {%8,%9}, {%0,%1,%2,%3};" \
                 : "+f"((c)[0]), "+f"((c)[1]), "+f"((c)[2]), "+f"((c)[3]) \
                 : "r"((a)[0]), "r"((a)[1]), "r"((a)[2]), "r"((a)[3]), \
                   "r"(b0), "r"(b1))

__device__ __forceinline__ uint32_t h2pack(float a, float b) {
    __half2 h = __floats2half2_rn(a, b);
    return *(uint32_t*)&h;
}

// swizzled byte offset: 64B rows, 16B unit u in 0..3, conflict-free XOR
__device__ __forceinline__ uint32_t sw64(uint32_t row, uint32_t u) {
    return row * 64 + ((u ^ (row >> 1)) & 3u) * 16;
}

// ---------------- small kernels --------------------------------------------
__global__ void reset_kernel() {
    if (threadIdx.x < NEXP) g_count[threadIdx.x] = 0;
}

__global__ void router_kernel(const float* __restrict__ x,
                              const float* __restrict__ wr,
                              float* __restrict__ dout,
                              int has_logits, int has_index) {
    int warp = threadIdx.x >> 5, lane = threadIdx.x & 31;
    int t = blockIdx.x * 8 + warp;
    if (t >= TOKENS) return;
    float acc[NEXP];
#pragma unroll
    for (int e = 0; e < NEXP; e++) acc[e] = 0.f;
    const float* xr = x + (size_t)t * DDIM;
    for (int d = lane; d < DDIM; d += 32) {
        float xv = xr[d];
#pragma unroll
        for (int e = 0; e < NEXP; e++) acc[e] += xv * wr[d * NEXP + e];
    }
#pragma unroll
    for (int e = 0; e < NEXP; e++) {
#pragma unroll
        for (int o = 16; o; o >>= 1)
            acc[e] += __shfl_xor_sync(0xffffffffu, acc[e], o);
    }
    if (lane == 0) {
        float mx = acc[0]; int mi = 0;
#pragma unroll
        for (int e = 1; e < NEXP; e++)
            if (acc[e] > mx) { mx = acc[e]; mi = e; }
        float s = 0.f;
#pragma unroll
        for (int e = 0; e < NEXP; e++) s += expf(acc[e] - mx);
        g_prob[t] = 1.0f / s;
        int slot = atomicAdd(&g_count[mi], 1);
        g_bucket[mi * TOKENS + slot] = t;
        if (has_logits) {
            float* lg = dout + (size_t)TOKENS * DDIM + (size_t)t * NEXP;
#pragma unroll
            for (int e = 0; e < NEXP; e++) lg[e] = acc[e];
        }
        if (has_index)
            dout[(size_t)TOKENS * DDIM + (size_t)TOKENS * NEXP + t] = (float)mi;
    }
}

// Transpose: in fp32 [E][R][C] -> fp16 [E][C][R].
// Output globals selected INSIDE device code (never pass __device__ symbols
// from host — GB300 ATS makes the host shadow silently writable).
template<bool W1SEL, int R, int C>
__global__ void transpose_h16(const float* __restrict__ in) {
    __half* __restrict__ o16 = W1SEL ? g_w1t : g_w2t;
    __shared__ float s[64][65];
    const int e = blockIdx.z;
    const float* I = in + (size_t)e * R * C;
    const size_t obase = (size_t)e * R * C;
    const int r0 = blockIdx.y * 64, c0 = blockIdx.x * 64;
    const int tid = threadIdx.x;
#pragma unroll
    for (int i = 0; i < 16; i++) {
        int idx = tid + i * 256;
        int rr = idx >> 6, cc = idx & 63;
        s[rr][cc] = I[(size_t)(r0 + rr) * C + c0 + cc];
    }
    __syncthreads();
#pragma unroll
    for (int i = 0; i < 8; i++) {
        int idx = tid + i * 256;
        int oc = idx >> 5, rp = idx & 31;
        float v0 = s[rp * 2][oc], v1 = s[rp * 2 + 1][oc];
        size_t o = obase + (size_t)(c0 + oc) * R + r0 + rp * 2;
        ((uint32_t*)o16)[o >> 1] = h2pack(v0, v1);
    }
}

// ---------------- mma.sync gather-GEMM -------------------------------------
// 128x128 CTA tile, K-chunk 32, 3-stage cp.async ring, single-product fp16.
// FIRST:  h1[tok] = relu(x[tok] @ w1[e] + b1[e])  -> fp16
// !FIRST: out[tok] = (h1[tok] @ w2[e] + b2[e]) * prob[tok]
template<bool FIRST, int KD, int ND>
__global__ __launch_bounds__(256, 2)
void moe_mma(const float* __restrict__ Asrc,
             const float* __restrict__ bias,
             float* __restrict__ Cout) {
    constexpr int NCH = KD / 32;                  // 32-wide K chunks
    constexpr uint32_t PLANE = 8192;              // 128 rows * 64 bytes
    constexpr uint32_t A_PL = 0, B_PL = PLANE;
    constexpr uint32_t STAGE = 2 * PLANE;         // 16 KB per stage, 3 stages

    extern __shared__ __align__(16) char sbuf[];
    __shared__ int stok[128];

    const int e = blockIdx.z;
    const int cnt = g_count[e];
    const int row0 = blockIdx.y * 128;
    if (row0 >= cnt) return;
    const int col0 = blockIdx.x * 128;
    const int tid = threadIdx.x;

    for (int i = tid; i < 128; i += 256) {
        int r = row0 + i;
        stok[i] = (r < cnt) ? g_bucket[e * TOKENS + r] : -1;
    }
    __syncthreads();

    const uint32_t sb = smem_to_u32(sbuf);

    // ---- loader: thread -> tile-row tid>>1, k-half (16 elems) tid&1 --------
    const int lrow = tid >> 1, half = tid & 1;
    const int tok = stok[lrow];
    const int tokc = tok < 0 ? 0 : tok;

    const float* aS = Asrc + (size_t)tokc * KD + half * 16;     // FIRST
    const __half* aHp = g_h1 + (size_t)tokc * KD + half * 16;   // !FIRST
    const __half* wp =
        (FIRST ? g_w1t : g_w2t) + ((size_t)e * ND + col0 + lrow) * KD + half * 16;
    const uint32_t d0 = sw64((uint32_t)lrow, (uint32_t)(half * 2));
    const uint32_t d1 = sw64((uint32_t)lrow, (uint32_t)(half * 2 + 1));

    auto issue = [&](int c) {
        const uint32_t bb = sb + (uint32_t)(c % 3) * STAGE;
        const int kk = c * 32;
        CP16(bb + B_PL + d0, wp + kk);
        CP16(bb + B_PL + d1, wp + kk + 8);
        if (FIRST) {
            float4 v0 = *(const float4*)(aS + kk);
            float4 v1 = *(const float4*)(aS + kk + 4);
            float4 v2 = *(const float4*)(aS + kk + 8);
            float4 v3 = *(const float4*)(aS + kk + 12);
            STS128(h2pack(v0.x, v0.y), h2pack(v0.z, v0.w),
                   h2pack(v1.x, v1.y), h2pack(v1.z, v1.w), bb + A_PL + d0);
            STS128(h2pack(v2.x, v2.y), h2pack(v2.z, v2.w),
                   h2pack(v3.x, v3.y), h2pack(v3.z, v3.w), bb + A_PL + d1);
        } else {
            CP16(bb + A_PL + d0, aHp + kk);
            CP16(bb + A_PL + d1, aHp + kk + 8);
        }
        asm volatile("cp.async.commit_group;" ::: "memory");
    };

    // ---- compute: 8 warps = 4(M) x 2(N); warp tile 32x64 -------------------
    const int w = tid >> 5, l = tid & 31;
    const int m0 = (w & 3) * 32;
    const int n0w = (w >> 2) * 64;
    float acc[2][8][4];
#pragma unroll
    for (int i = 0; i < 2; i++)
#pragma unroll
        for (int j = 0; j < 8; j++)
#pragma unroll
            for (int q = 0; q < 4; q++) acc[i][j][q] = 0.f;

    auto compute = [&](int c) {
        const uint32_t bb = sb + (uint32_t)(c % 3) * STAGE;
#pragma unroll
        for (int s = 0; s < 2; s++) {            // two k16 substeps of chunk
            uint32_t aH[2][4];
#pragma unroll
            for (int i = 0; i < 2; i++) {
                uint32_t ra = bb + sw64((uint32_t)(m0 + i * 16 + (l & 15)),
                                        (uint32_t)(2 * s + (l >> 4)));
                LDSM4(aH[i], ra + A_PL);
            }
#pragma unroll
            for (int jj = 0; jj < 4; jj++) {
                uint32_t rb = bb + sw64((uint32_t)(n0w + jj * 16 + (l & 7) + ((l >> 4) << 3)),
                                        (uint32_t)(2 * s + ((l >> 3) & 1)));
                uint32_t tB[4];
                LDSM4(tB, rb + B_PL);
#pragma unroll
                for (int i = 0; i < 2; i++) {
                    MMA(acc[i][2 * jj],     aH[i], tB[0], tB[1]);
                    MMA(acc[i][2 * jj + 1], aH[i], tB[2], tB[3]);
                }
            }
        }
    };

    // ---- 3-stage pipeline, ONE barrier per chunk ---------------------------
    // Order: wait -> sync -> issue(c+2) -> compute(c).  A fast warp cannot
    // issue into stage (c+2)%3 until every warp has passed this chunk's sync,
    // which is after their compute(c-1) (the reader of that stage) finished.
    issue(0);
    issue(1);
    for (int c = 0; c < NCH; c++) {
        if (c + 1 < NCH) {
            asm volatile("cp.async.wait_group 1;" ::: "memory");
        } else {
            asm volatile("cp.async.wait_group 0;" ::: "memory");
        }
        __syncthreads();
        if (c + 2 < NCH) issue(c + 2);
        compute(c);
    }

    // ---- epilogue ----------------------------------------------------------
    const float* bptr = bias + (size_t)e * ND;
#pragma unroll
    for (int i = 0; i < 2; i++) {
#pragma unroll
        for (int h2 = 0; h2 < 2; h2++) {
            int mrow = m0 + i * 16 + (l >> 2) + h2 * 8;
            int t2 = stok[mrow];
            if (t2 < 0) continue;
            float p = FIRST ? 0.f : g_prob[t2];
#pragma unroll
            for (int j = 0; j < 8; j++) {
                int col = col0 + n0w + j * 8 + (l & 3) * 2;
                float v0 = acc[i][j][h2 * 2 + 0] + bptr[col];
                float v1 = acc[i][j][h2 * 2 + 1] + bptr[col + 1];
                if (FIRST) {
                    v0 = v0 > 0.f ? v0 : 0.f;
                    v1 = v1 > 0.f ? v1 : 0.f;
                    *(uint32_t*)(g_h1 + (size_t)t2 * FDIM + col) = h2pack(v0, v1);
                } else {
                    *(float2*)(Cout + (size_t)t2 * DDIM + col) =
                        make_float2(v0 * p, v1 * p);
                }
            }
        }
    }
}

// ---------------- launch ----------------------------------------------------
extern "C" void kernel_launch(void* const* d_in, const int* in_sizes, int n_in,
                              void* d_out, int out_size) {
    const float* x  = (const float*)d_in[0];   // [4,1024,768]
    const float* wr = (const float*)d_in[1];   // [768,8]
    const float* w1 = (const float*)d_in[2];   // [8,768,3072]
    const float* b1 = (const float*)d_in[3];   // [8,3072]
    const float* w2 = (const float*)d_in[4];   // [8,3072,768]
    const float* b2 = (const float*)d_in[5];   // [8,768]
    float* out = (float*)d_out;

    const int hid = TOKENS * DDIM;
    int has_logits = (out_size >= hid + TOKENS * NEXP) ? 1 : 0;
    int has_index  = (out_size >= hid + TOKENS * NEXP + TOKENS) ? 1 : 0;

    const int SMEM_BYTES = 3 * 16384;   // 48 KB dynamic (3-stage ring)
    cudaFuncSetAttribute(moe_mma<true, DDIM, FDIM>,
                         cudaFuncAttributeMaxDynamicSharedMemorySize, SMEM_BYTES);
    cudaFuncSetAttribute(moe_mma<false, FDIM, DDIM>,
                         cudaFuncAttributeMaxDynamicSharedMemorySize, SMEM_BYTES);

    reset_kernel<<<1, 32>>>();
    router_kernel<<<TOKENS / 8, 256>>>(x, wr, out, has_logits, has_index);

    transpose_h16<true,  DDIM, FDIM>
        <<<dim3(FDIM / 64, DDIM / 64, NEXP), 256>>>(w1);
    transpose_h16<false, FDIM, DDIM>
        <<<dim3(DDIM / 64, FDIM / 64, NEXP), 256>>>(w2);

    // GEMM1: [cnt x 768] @ w1 -> relu -> g_h1 (fp16)
    moe_mma<true, DDIM, FDIM>
        <<<dim3(FDIM / 128, TOKENS / 128, NEXP), 256, SMEM_BYTES>>>(x, b1, nullptr);
    // GEMM2: [cnt x 3072] @ w2 -> +bias, *prob -> out
    moe_mma<false, FDIM, DDIM>
        <<<dim3(DDIM / 128, TOKENS / 128, NEXP), 256, SMEM_BYTES>>>(nullptr, b2, out);
}